// round 13
// baseline (speedup 1.0000x reference)
#include <cuda_runtime.h>
#include <cuda_bf16.h>
#include <math.h>

#define B_ 4
#define S_ 2048
#define DIN 2048
#define DOUT 2048
#define DEPTH 11
#define NLEV (DEPTH + 1)          // 12
#define NNODES 4095
#define NTOK (B_ * S_)            // 8192
#define NLEAF 2048
#define LEAF0 2047

#define TRN_BX 128                // ceil(4095/32)

// accum config
#define TPC 8                     // tokens per CTA
#define HSZ 128                   // node hash table size (union <= 96)

// Static scratch
__device__ float          g_wout_t[(size_t)NNODES * DOUT];
__device__ float          g_gel[NTOK * NLEV];
__device__ unsigned short g_leaf[NTOK];
__device__ int            g_hist[NLEAF];     // zero-init; re-zeroed by scan_scatter
__device__ int            g_perm[NTOK];

__device__ __forceinline__ float gelu_exact(float s) {
    return 0.5f * s * (1.0f + erff(s * 0.70710678118654752440f));
}

// ---------------------------------------------------------------------------
// Fused (R9/R12 winner, verbatim): even blocks = traverse (1 token per
// 128-thread CTA, 4 warps x 512 dims); odd blocks = transpose w_out.
// Levels 0-4 default-cached (L1 reuse); levels 5-11 __ldcg (L2-only).
// ---------------------------------------------------------------------------
__global__ __launch_bounds__(128) void fused_traverse_kernel(
    const float* __restrict__ x,
    const float* __restrict__ w_in,
    const float* __restrict__ w_out)
{
    __shared__ float tile[32][33];
    __shared__ float part[2][4];

    if (blockIdx.x & 1) {
        // ---- transpose partition: w_out [DOUT,NNODES] -> g_wout_t ----
        const int tb  = blockIdx.x >> 1;
        const int nx0 = (tb % TRN_BX) * 32;
        const int dy0 = (tb / TRN_BX) * 32;
        const int tx  = threadIdx.x & 31;
        const int ty  = threadIdx.x >> 5;          // 0..3
#pragma unroll
        for (int j = 0; j < 32; j += 4) {
            int r = dy0 + ty + j, c = nx0 + tx;
            float v = 0.f;
            if (c < NNODES) v = w_out[(size_t)r * NNODES + c];
            tile[ty + j][tx] = v;
        }
        __syncthreads();
#pragma unroll
        for (int j = 0; j < 32; j += 4) {
            int r = nx0 + ty + j, c = dy0 + tx;
            if (r < NNODES) g_wout_t[(size_t)r * DOUT + c] = tile[tx][ty + j];
        }
        return;
    }

    // ---- traverse partition: 4 warps x 512 dims, one token ----
    const int tok  = blockIdx.x >> 1;
    const int q    = threadIdx.x >> 5;
    const int lane = threadIdx.x & 31;

    const float4* __restrict__ xq =
        reinterpret_cast<const float4*>(x + (size_t)tok * DIN) + q * 128;
    float4 xr[4];
#pragma unroll
    for (int j = 0; j < 4; j++) xr[j] = xq[j * 32 + lane];

    const float4* __restrict__ wb =
        reinterpret_cast<const float4*>(w_in) + q * 128;

    int cur = 0;
#pragma unroll
    for (int l = 0; l < NLEV; l++) {
        const float4* __restrict__ w = wb + (size_t)cur * 512;
        float4 a, b, c, d;
        if (l < 5) {                       // shallow: keep in L1 (high reuse)
            a = w[0 * 32 + lane];
            b = w[1 * 32 + lane];
            c = w[2 * 32 + lane];
            d = w[3 * 32 + lane];
        } else {                           // deep: L2-only, don't thrash L1
            a = __ldcg(&w[0 * 32 + lane]);
            b = __ldcg(&w[1 * 32 + lane]);
            c = __ldcg(&w[2 * 32 + lane]);
            d = __ldcg(&w[3 * 32 + lane]);
        }
        float p0 = xr[0].x * a.x + xr[0].y * a.y + xr[0].z * a.z + xr[0].w * a.w;
        float p1 = xr[1].x * b.x + xr[1].y * b.y + xr[1].z * b.z + xr[1].w * b.w;
        float p2 = xr[2].x * c.x + xr[2].y * c.y + xr[2].z * c.z + xr[2].w * c.w;
        float p3 = xr[3].x * d.x + xr[3].y * d.y + xr[3].z * d.z + xr[3].w * d.w;
        float p = (p0 + p1) + (p2 + p3);
#pragma unroll
        for (int off = 16; off > 0; off >>= 1)
            p += __shfl_xor_sync(0xffffffffu, p, off);
        if (lane == 0) part[l & 1][q] = p;
        __syncthreads();
        const float s = (part[l & 1][0] + part[l & 1][1])
                      + (part[l & 1][2] + part[l & 1][3]);
        if (threadIdx.x == 0) g_gel[tok * NLEV + l] = gelu_exact(s);
        cur = cur * 2 + 1 + (s >= 0.0f ? 1 : 0);
    }
    if (threadIdx.x == 0) {
        const int leaf = ((cur - 1) >> 1) - LEAF0;
        g_leaf[tok] = (unsigned short)leaf;
        atomicAdd(&g_hist[leaf], 1);
    }
}

// ---------------------------------------------------------------------------
// Fused scan + scatter, one CTA of 1024 threads. Re-zeroes g_hist for the
// next graph replay (statics start zeroed for the first call).
// ---------------------------------------------------------------------------
__global__ __launch_bounds__(1024) void scan_scatter_kernel() {
    __shared__ int s0[NLEAF];
    __shared__ int s1[NLEAF];
    const int t = threadIdx.x;
    s0[t]        = g_hist[t];
    s0[t + 1024] = g_hist[t + 1024];
    g_hist[t]        = 0;
    g_hist[t + 1024] = 0;
    __syncthreads();
    int* src = s0; int* dst = s1;
    for (int off = 1; off < NLEAF; off <<= 1) {
#pragma unroll
        for (int k = 0; k < 2; k++) {
            int i = t + k * 1024;
            int v = src[i];
            if (i >= off) v += src[i - off];
            dst[i] = v;
        }
        __syncthreads();
        int* tmp = src; src = dst; dst = tmp;
    }
#pragma unroll
    for (int k = 0; k < 2; k++) {
        int i = t + k * 1024;
        dst[i] = (i == 0) ? 0 : src[i - 1];
    }
    __syncthreads();
#pragma unroll
    for (int k = 0; k < 8; k++) {
        int tok  = t + k * 1024;
        int leaf = (int)g_leaf[tok];
        int pos  = atomicAdd(&dst[leaf], 1);
        g_perm[pos] = tok;
    }
}

// ---------------------------------------------------------------------------
// Accumulate: 512-thread CTA = 8 leaf-sorted tokens; thread owns ONE float4.
// Distinct rows double-buffered through smem via cp.async (LDGSTS): the
// prefetch consumes NO registers, and since each thread reads only the 16B
// it copied, cp.async.wait_group alone orders the data (no __syncthreads
// inside the loop).
// ---------------------------------------------------------------------------
__global__ __launch_bounds__(512, 2) void accum_kernel(float* __restrict__ out) {
    __shared__ int    s_key[HSZ];
    __shared__ float  s_gl[HSZ][TPC];
    __shared__ int    s_list[HSZ];
    __shared__ int    s_cnt;
    __shared__ int    s_tok[TPC];
    __shared__ int    s_leafp1[TPC];
    __shared__ float4 s_buf[2][512];       // double-buffered row staging

    const int tid = threadIdx.x;

    if (tid < HSZ) s_key[tid] = -1;
#pragma unroll
    for (int k = tid; k < HSZ * TPC; k += 512) (&s_gl[0][0])[k] = 0.0f;
    if (tid == 0) s_cnt = 0;
    if (tid < TPC) {
        int tk = g_perm[blockIdx.x * TPC + tid];
        s_tok[tid]    = tk;
        s_leafp1[tid] = ((int)g_leaf[tk] + LEAF0) + 1;
    }
    __syncthreads();

    if (tid < TPC * NLEV) {
        const int t = tid / NLEV;
        const int l = tid % NLEV;
        const int node = (s_leafp1[t] >> (DEPTH - l)) - 1;
        const float gl = g_gel[s_tok[t] * NLEV + l];
        unsigned slot = ((unsigned)node * 2654435761u >> 16) & (HSZ - 1);
        while (true) {
            int prev = atomicCAS(&s_key[slot], -1, node);
            if (prev == -1 || prev == node) break;
            slot = (slot + 1) & (HSZ - 1);
        }
        s_gl[slot][t] = gl;
    }
    __syncthreads();

    if (tid < HSZ) {
        if (s_key[tid] != -1) {
            int pos = atomicAdd(&s_cnt, 1);
            s_list[pos] = tid;
        }
    }
    __syncthreads();
    const int cnt = s_cnt;

    float4 acc[TPC];
#pragma unroll
    for (int t = 0; t < TPC; t++) acc[t] = make_float4(0.f, 0.f, 0.f, 0.f);

    // smem destinations for this thread's 16B slice in each buffer
    const unsigned dst0 = (unsigned)__cvta_generic_to_shared(&s_buf[0][tid]);
    const unsigned dst1 = (unsigned)__cvta_generic_to_shared(&s_buf[1][tid]);

    // prologue: stage row 0 into buffer 0
    {
        const float4* src = reinterpret_cast<const float4*>(
            g_wout_t + (size_t)s_key[s_list[0]] * DOUT) + tid;
        asm volatile("cp.async.cg.shared.global [%0], [%1], 16;\n"
                     :: "r"(dst0), "l"(src) : "memory");
        asm volatile("cp.async.commit_group;\n" ::: "memory");
    }

    for (int i = 0; i < cnt; i++) {
        if (i + 1 < cnt) {
            // stage row i+1 into the other buffer
            const float4* src = reinterpret_cast<const float4*>(
                g_wout_t + (size_t)s_key[s_list[i + 1]] * DOUT) + tid;
            const unsigned dst = ((i + 1) & 1) ? dst1 : dst0;
            asm volatile("cp.async.cg.shared.global [%0], [%1], 16;\n"
                         :: "r"(dst), "l"(src) : "memory");
            asm volatile("cp.async.commit_group;\n" ::: "memory");
            asm volatile("cp.async.wait_group 1;\n" ::: "memory");  // row i done
        } else {
            asm volatile("cp.async.wait_group 0;\n" ::: "memory");
        }

        const float4 r = s_buf[i & 1][tid];
        const int slot = s_list[i];
        float gl[TPC];
#pragma unroll
        for (int t = 0; t < TPC; t++) gl[t] = s_gl[slot][t];   // warp-uniform bcast
#pragma unroll
        for (int t = 0; t < TPC; t++) {
            acc[t].x += gl[t] * r.x;
            acc[t].y += gl[t] * r.y;
            acc[t].z += gl[t] * r.z;
            acc[t].w += gl[t] * r.w;
        }
    }

#pragma unroll
    for (int t = 0; t < TPC; t++)
        reinterpret_cast<float4*>(out + (size_t)s_tok[t] * DOUT)[tid] = acc[t];
}

// ---------------------------------------------------------------------------
extern "C" void kernel_launch(void* const* d_in, const int* in_sizes, int n_in,
                              void* d_out, int out_size) {
    const float* x     = (const float*)d_in[0];
    const float* w_in  = (const float*)d_in[1];
    const float* w_out = (const float*)d_in[2];
    float* out = (float*)d_out;

    fused_traverse_kernel<<<2 * NTOK, 128>>>(x, w_in, w_out);  // even=traverse, odd=transpose
    scan_scatter_kernel<<<1, 1024>>>();
    accum_kernel<<<NTOK / TPC, 512>>>(out);
}

// round 14
// speedup vs baseline: 1.0199x; 1.0199x over previous
#include <cuda_runtime.h>
#include <cuda_bf16.h>
#include <math.h>

#define B_ 4
#define S_ 2048
#define DIN 2048
#define DOUT 2048
#define DEPTH 11
#define NLEV (DEPTH + 1)          // 12
#define NNODES 4095
#define NTOK (B_ * S_)            // 8192
#define NLEAF 2048
#define LEAF0 2047

#define TRN_BX 128                // ceil(4095/32)

// accum config
#define TPC 8                     // tokens per CTA
#define HSZ 128                   // node hash table size (union <= 96)
#define STAGES 8                  // cp.async pipeline depth (hides ~500cyc L2 lat)

// Static scratch
__device__ float          g_wout_t[(size_t)NNODES * DOUT];
__device__ float          g_gel[NTOK * NLEV];
__device__ unsigned short g_leaf[NTOK];
__device__ int            g_hist[NLEAF];     // zero-init; re-zeroed by scan_scatter
__device__ int            g_perm[NTOK];

__device__ __forceinline__ float gelu_exact(float s) {
    return 0.5f * s * (1.0f + erff(s * 0.70710678118654752440f));
}

// ---------------------------------------------------------------------------
// Fused (R9/R12 winner, verbatim): even blocks = traverse (1 token per
// 128-thread CTA, 4 warps x 512 dims); odd blocks = transpose w_out.
// Levels 0-4 default-cached (L1 reuse); levels 5-11 __ldcg (L2-only).
// ---------------------------------------------------------------------------
__global__ __launch_bounds__(128) void fused_traverse_kernel(
    const float* __restrict__ x,
    const float* __restrict__ w_in,
    const float* __restrict__ w_out)
{
    __shared__ float tile[32][33];
    __shared__ float part[2][4];

    if (blockIdx.x & 1) {
        // ---- transpose partition: w_out [DOUT,NNODES] -> g_wout_t ----
        const int tb  = blockIdx.x >> 1;
        const int nx0 = (tb % TRN_BX) * 32;
        const int dy0 = (tb / TRN_BX) * 32;
        const int tx  = threadIdx.x & 31;
        const int ty  = threadIdx.x >> 5;          // 0..3
#pragma unroll
        for (int j = 0; j < 32; j += 4) {
            int r = dy0 + ty + j, c = nx0 + tx;
            float v = 0.f;
            if (c < NNODES) v = w_out[(size_t)r * NNODES + c];
            tile[ty + j][tx] = v;
        }
        __syncthreads();
#pragma unroll
        for (int j = 0; j < 32; j += 4) {
            int r = nx0 + ty + j, c = dy0 + tx;
            if (r < NNODES) g_wout_t[(size_t)r * DOUT + c] = tile[tx][ty + j];
        }
        return;
    }

    // ---- traverse partition: 4 warps x 512 dims, one token ----
    const int tok  = blockIdx.x >> 1;
    const int q    = threadIdx.x >> 5;
    const int lane = threadIdx.x & 31;

    const float4* __restrict__ xq =
        reinterpret_cast<const float4*>(x + (size_t)tok * DIN) + q * 128;
    float4 xr[4];
#pragma unroll
    for (int j = 0; j < 4; j++) xr[j] = xq[j * 32 + lane];

    const float4* __restrict__ wb =
        reinterpret_cast<const float4*>(w_in) + q * 128;

    int cur = 0;
#pragma unroll
    for (int l = 0; l < NLEV; l++) {
        const float4* __restrict__ w = wb + (size_t)cur * 512;
        float4 a, b, c, d;
        if (l < 5) {                       // shallow: keep in L1 (high reuse)
            a = w[0 * 32 + lane];
            b = w[1 * 32 + lane];
            c = w[2 * 32 + lane];
            d = w[3 * 32 + lane];
        } else {                           // deep: L2-only, don't thrash L1
            a = __ldcg(&w[0 * 32 + lane]);
            b = __ldcg(&w[1 * 32 + lane]);
            c = __ldcg(&w[2 * 32 + lane]);
            d = __ldcg(&w[3 * 32 + lane]);
        }
        float p0 = xr[0].x * a.x + xr[0].y * a.y + xr[0].z * a.z + xr[0].w * a.w;
        float p1 = xr[1].x * b.x + xr[1].y * b.y + xr[1].z * b.z + xr[1].w * b.w;
        float p2 = xr[2].x * c.x + xr[2].y * c.y + xr[2].z * c.z + xr[2].w * c.w;
        float p3 = xr[3].x * d.x + xr[3].y * d.y + xr[3].z * d.z + xr[3].w * d.w;
        float p = (p0 + p1) + (p2 + p3);
#pragma unroll
        for (int off = 16; off > 0; off >>= 1)
            p += __shfl_xor_sync(0xffffffffu, p, off);
        if (lane == 0) part[l & 1][q] = p;
        __syncthreads();
        const float s = (part[l & 1][0] + part[l & 1][1])
                      + (part[l & 1][2] + part[l & 1][3]);
        if (threadIdx.x == 0) g_gel[tok * NLEV + l] = gelu_exact(s);
        cur = cur * 2 + 1 + (s >= 0.0f ? 1 : 0);
    }
    if (threadIdx.x == 0) {
        const int leaf = ((cur - 1) >> 1) - LEAF0;
        g_leaf[tok] = (unsigned short)leaf;
        atomicAdd(&g_hist[leaf], 1);
    }
}

// ---------------------------------------------------------------------------
// Fused scan + scatter, one CTA of 1024 threads. Re-zeroes g_hist for the
// next graph replay (statics start zeroed for the first call).
// ---------------------------------------------------------------------------
__global__ __launch_bounds__(1024) void scan_scatter_kernel() {
    __shared__ int s0[NLEAF];
    __shared__ int s1[NLEAF];
    const int t = threadIdx.x;
    s0[t]        = g_hist[t];
    s0[t + 1024] = g_hist[t + 1024];
    g_hist[t]        = 0;
    g_hist[t + 1024] = 0;
    __syncthreads();
    int* src = s0; int* dst = s1;
    for (int off = 1; off < NLEAF; off <<= 1) {
#pragma unroll
        for (int k = 0; k < 2; k++) {
            int i = t + k * 1024;
            int v = src[i];
            if (i >= off) v += src[i - off];
            dst[i] = v;
        }
        __syncthreads();
        int* tmp = src; src = dst; dst = tmp;
    }
#pragma unroll
    for (int k = 0; k < 2; k++) {
        int i = t + k * 1024;
        dst[i] = (i == 0) ? 0 : src[i - 1];
    }
    __syncthreads();
#pragma unroll
    for (int k = 0; k < 8; k++) {
        int tok  = t + k * 1024;
        int leaf = (int)g_leaf[tok];
        int pos  = atomicAdd(&dst[leaf], 1);
        g_perm[pos] = tok;
    }
}

// ---------------------------------------------------------------------------
// Accumulate: 512-thread CTA = 8 leaf-sorted tokens; thread owns ONE float4.
// Distinct rows streamed through an 8-deep cp.async smem pipeline: one
// commit_group per iteration (possibly empty), so `wait_group STAGES-1`
// always guarantees row i is resident. Each thread reads only the 16B it
// copied -> no __syncthreads in the loop. Prefetch uses zero registers.
// ---------------------------------------------------------------------------
__global__ __launch_bounds__(512, 2) void accum_kernel(float* __restrict__ out) {
    __shared__ int    s_key[HSZ];
    __shared__ float  s_gl[HSZ][TPC];
    __shared__ int    s_list[HSZ];
    __shared__ int    s_cnt;
    __shared__ int    s_tok[TPC];
    __shared__ int    s_leafp1[TPC];
    __shared__ float4 s_buf[STAGES][512];     // 64KB row staging

    const int tid = threadIdx.x;

    if (tid < HSZ) s_key[tid] = -1;
#pragma unroll
    for (int k = tid; k < HSZ * TPC; k += 512) (&s_gl[0][0])[k] = 0.0f;
    if (tid == 0) s_cnt = 0;
    if (tid < TPC) {
        int tk = g_perm[blockIdx.x * TPC + tid];
        s_tok[tid]    = tk;
        s_leafp1[tid] = ((int)g_leaf[tk] + LEAF0) + 1;
    }
    __syncthreads();

    if (tid < TPC * NLEV) {
        const int t = tid / NLEV;
        const int l = tid % NLEV;
        const int node = (s_leafp1[t] >> (DEPTH - l)) - 1;
        const float gl = g_gel[s_tok[t] * NLEV + l];
        unsigned slot = ((unsigned)node * 2654435761u >> 16) & (HSZ - 1);
        while (true) {
            int prev = atomicCAS(&s_key[slot], -1, node);
            if (prev == -1 || prev == node) break;
            slot = (slot + 1) & (HSZ - 1);
        }
        s_gl[slot][t] = gl;
    }
    __syncthreads();

    if (tid < HSZ) {
        if (s_key[tid] != -1) {
            int pos = atomicAdd(&s_cnt, 1);
            s_list[pos] = tid;
        }
    }
    __syncthreads();
    const int cnt = s_cnt;

    float4 acc[TPC];
#pragma unroll
    for (int t = 0; t < TPC; t++) acc[t] = make_float4(0.f, 0.f, 0.f, 0.f);

    // prologue: stage rows 0 .. STAGES-2, one commit group each
#pragma unroll
    for (int j = 0; j < STAGES - 1; j++) {
        if (j < cnt) {
            const float4* src = reinterpret_cast<const float4*>(
                g_wout_t + (size_t)s_key[s_list[j]] * DOUT) + tid;
            const unsigned dst =
                (unsigned)__cvta_generic_to_shared(&s_buf[j][tid]);
            asm volatile("cp.async.cg.shared.global [%0], [%1], 16;\n"
                         :: "r"(dst), "l"(src) : "memory");
        }
        asm volatile("cp.async.commit_group;\n" ::: "memory");
    }

    for (int i = 0; i < cnt; i++) {
        // issue row i+STAGES-1 (or an empty group to keep the count uniform)
        const int j = i + STAGES - 1;
        if (j < cnt) {
            const float4* src = reinterpret_cast<const float4*>(
                g_wout_t + (size_t)s_key[s_list[j]] * DOUT) + tid;
            const unsigned dst =
                (unsigned)__cvta_generic_to_shared(&s_buf[j & (STAGES - 1)][tid]);
            asm volatile("cp.async.cg.shared.global [%0], [%1], 16;\n"
                         :: "r"(dst), "l"(src) : "memory");
        }
        asm volatile("cp.async.commit_group;\n" ::: "memory");
        asm volatile("cp.async.wait_group %0;\n" :: "n"(STAGES - 1) : "memory");

        const float4 r = s_buf[i & (STAGES - 1)][tid];
        const int slot = s_list[i];
        float gl[TPC];
#pragma unroll
        for (int t = 0; t < TPC; t++) gl[t] = s_gl[slot][t];   // warp-uniform bcast
#pragma unroll
        for (int t = 0; t < TPC; t++) {
            acc[t].x += gl[t] * r.x;
            acc[t].y += gl[t] * r.y;
            acc[t].z += gl[t] * r.z;
            acc[t].w += gl[t] * r.w;
        }
    }

#pragma unroll
    for (int t = 0; t < TPC; t++)
        reinterpret_cast<float4*>(out + (size_t)s_tok[t] * DOUT)[tid] = acc[t];
}

// ---------------------------------------------------------------------------
extern "C" void kernel_launch(void* const* d_in, const int* in_sizes, int n_in,
                              void* d_out, int out_size) {
    const float* x     = (const float*)d_in[0];
    const float* w_in  = (const float*)d_in[1];
    const float* w_out = (const float*)d_in[2];
    float* out = (float*)d_out;

    fused_traverse_kernel<<<2 * NTOK, 128>>>(x, w_in, w_out);  // even=traverse, odd=transpose
    scan_scatter_kernel<<<1, 1024>>>();
    accum_kernel<<<NTOK / TPC, 512>>>(out);
}

// round 15
// speedup vs baseline: 1.0495x; 1.0290x over previous
#include <cuda_runtime.h>
#include <cuda_bf16.h>
#include <math.h>

#define B_ 4
#define S_ 2048
#define DIN 2048
#define DOUT 2048
#define DEPTH 11
#define NLEV (DEPTH + 1)          // 12
#define NNODES 4095
#define NTOK (B_ * S_)            // 8192
#define NLEAF 2048
#define LEAF0 2047

#define TRN_BX 128                // ceil(4095/32)

// accum config
#define TPC 8                     // tokens per CTA
#define HSZ 128                   // node hash table size (union <= 96)

// Static scratch
__device__ float          g_wout_t[(size_t)NNODES * DOUT];
__device__ float          g_gel[NTOK * NLEV];
__device__ unsigned short g_leaf[NTOK];
__device__ int            g_hist[NLEAF];     // zero-init; re-zeroed by scan_scatter
__device__ int            g_perm[NTOK];

__device__ __forceinline__ float gelu_exact(float s) {
    return 0.5f * s * (1.0f + erff(s * 0.70710678118654752440f));
}

// ---------------------------------------------------------------------------
// Fused (R9/R12 winner, verbatim): even blocks = traverse (1 token per
// 128-thread CTA, 4 warps x 512 dims); odd blocks = transpose w_out.
// Levels 0-4 default-cached (L1 reuse); levels 5-11 __ldcg (L2-only).
// ---------------------------------------------------------------------------
__global__ __launch_bounds__(128) void fused_traverse_kernel(
    const float* __restrict__ x,
    const float* __restrict__ w_in,
    const float* __restrict__ w_out)
{
    __shared__ float tile[32][33];
    __shared__ float part[2][4];

    if (blockIdx.x & 1) {
        // ---- transpose partition: w_out [DOUT,NNODES] -> g_wout_t ----
        const int tb  = blockIdx.x >> 1;
        const int nx0 = (tb % TRN_BX) * 32;
        const int dy0 = (tb / TRN_BX) * 32;
        const int tx  = threadIdx.x & 31;
        const int ty  = threadIdx.x >> 5;          // 0..3
#pragma unroll
        for (int j = 0; j < 32; j += 4) {
            int r = dy0 + ty + j, c = nx0 + tx;
            float v = 0.f;
            if (c < NNODES) v = w_out[(size_t)r * NNODES + c];
            tile[ty + j][tx] = v;
        }
        __syncthreads();
#pragma unroll
        for (int j = 0; j < 32; j += 4) {
            int r = nx0 + ty + j, c = dy0 + tx;
            if (r < NNODES) g_wout_t[(size_t)r * DOUT + c] = tile[tx][ty + j];
        }
        return;
    }

    // ---- traverse partition: 4 warps x 512 dims, one token ----
    const int tok  = blockIdx.x >> 1;
    const int q    = threadIdx.x >> 5;
    const int lane = threadIdx.x & 31;

    const float4* __restrict__ xq =
        reinterpret_cast<const float4*>(x + (size_t)tok * DIN) + q * 128;
    float4 xr[4];
#pragma unroll
    for (int j = 0; j < 4; j++) xr[j] = xq[j * 32 + lane];

    const float4* __restrict__ wb =
        reinterpret_cast<const float4*>(w_in) + q * 128;

    int cur = 0;
#pragma unroll
    for (int l = 0; l < NLEV; l++) {
        const float4* __restrict__ w = wb + (size_t)cur * 512;
        float4 a, b, c, d;
        if (l < 5) {                       // shallow: keep in L1 (high reuse)
            a = w[0 * 32 + lane];
            b = w[1 * 32 + lane];
            c = w[2 * 32 + lane];
            d = w[3 * 32 + lane];
        } else {                           // deep: L2-only, don't thrash L1
            a = __ldcg(&w[0 * 32 + lane]);
            b = __ldcg(&w[1 * 32 + lane]);
            c = __ldcg(&w[2 * 32 + lane]);
            d = __ldcg(&w[3 * 32 + lane]);
        }
        float p0 = xr[0].x * a.x + xr[0].y * a.y + xr[0].z * a.z + xr[0].w * a.w;
        float p1 = xr[1].x * b.x + xr[1].y * b.y + xr[1].z * b.z + xr[1].w * b.w;
        float p2 = xr[2].x * c.x + xr[2].y * c.y + xr[2].z * c.z + xr[2].w * c.w;
        float p3 = xr[3].x * d.x + xr[3].y * d.y + xr[3].z * d.z + xr[3].w * d.w;
        float p = (p0 + p1) + (p2 + p3);
#pragma unroll
        for (int off = 16; off > 0; off >>= 1)
            p += __shfl_xor_sync(0xffffffffu, p, off);
        if (lane == 0) part[l & 1][q] = p;
        __syncthreads();
        const float s = (part[l & 1][0] + part[l & 1][1])
                      + (part[l & 1][2] + part[l & 1][3]);
        if (threadIdx.x == 0) g_gel[tok * NLEV + l] = gelu_exact(s);
        cur = cur * 2 + 1 + (s >= 0.0f ? 1 : 0);
    }
    if (threadIdx.x == 0) {
        const int leaf = ((cur - 1) >> 1) - LEAF0;
        g_leaf[tok] = (unsigned short)leaf;
        atomicAdd(&g_hist[leaf], 1);
    }
}

// ---------------------------------------------------------------------------
// Fused scan + scatter, one CTA of 1024 threads. Re-zeroes g_hist for the
// next graph replay (statics start zeroed for the first call).
// ---------------------------------------------------------------------------
__global__ __launch_bounds__(1024) void scan_scatter_kernel() {
    __shared__ int s0[NLEAF];
    __shared__ int s1[NLEAF];
    const int t = threadIdx.x;
    s0[t]        = g_hist[t];
    s0[t + 1024] = g_hist[t + 1024];
    g_hist[t]        = 0;
    g_hist[t + 1024] = 0;
    __syncthreads();
    int* src = s0; int* dst = s1;
    for (int off = 1; off < NLEAF; off <<= 1) {
#pragma unroll
        for (int k = 0; k < 2; k++) {
            int i = t + k * 1024;
            int v = src[i];
            if (i >= off) v += src[i - off];
            dst[i] = v;
        }
        __syncthreads();
        int* tmp = src; src = dst; dst = tmp;
    }
#pragma unroll
    for (int k = 0; k < 2; k++) {
        int i = t + k * 1024;
        dst[i] = (i == 0) ? 0 : src[i - 1];
    }
    __syncthreads();
#pragma unroll
    for (int k = 0; k < 8; k++) {
        int tok  = t + k * 1024;
        int leaf = (int)g_leaf[tok];
        int pos  = atomicAdd(&dst[leaf], 1);
        g_perm[pos] = tok;
    }
}

// ---------------------------------------------------------------------------
// Accumulate: 512-thread CTA = 8 leaf-sorted tokens; thread owns ONE float4.
// R12 structure with the distinct-row loop unrolled by 2: two independent
// LDG.128 in flight per iteration (MLP=2). No min-blocks clamp so ptxas
// never spills; if regs stay <=64 we keep 2 CTAs/SM as well.
// ---------------------------------------------------------------------------
__global__ __launch_bounds__(512) void accum_kernel(float* __restrict__ out) {
    __shared__ int   s_key[HSZ];
    __shared__ float s_gl[HSZ][TPC];
    __shared__ int   s_list[HSZ];
    __shared__ int   s_cnt;
    __shared__ int   s_tok[TPC];
    __shared__ int   s_leafp1[TPC];

    const int tid = threadIdx.x;

    if (tid < HSZ) s_key[tid] = -1;
#pragma unroll
    for (int k = tid; k < HSZ * TPC; k += 512) (&s_gl[0][0])[k] = 0.0f;
    if (tid == 0) s_cnt = 0;
    if (tid < TPC) {
        int tk = g_perm[blockIdx.x * TPC + tid];
        s_tok[tid]    = tk;
        s_leafp1[tid] = ((int)g_leaf[tk] + LEAF0) + 1;
    }
    __syncthreads();

    if (tid < TPC * NLEV) {
        const int t = tid / NLEV;
        const int l = tid % NLEV;
        const int node = (s_leafp1[t] >> (DEPTH - l)) - 1;
        const float gl = g_gel[s_tok[t] * NLEV + l];
        unsigned slot = ((unsigned)node * 2654435761u >> 16) & (HSZ - 1);
        while (true) {
            int prev = atomicCAS(&s_key[slot], -1, node);
            if (prev == -1 || prev == node) break;
            slot = (slot + 1) & (HSZ - 1);
        }
        s_gl[slot][t] = gl;
    }
    __syncthreads();

    if (tid < HSZ) {
        if (s_key[tid] != -1) {
            int pos = atomicAdd(&s_cnt, 1);
            s_list[pos] = tid;
        }
    }
    __syncthreads();
    const int cnt = s_cnt;

    float4 acc[TPC];
#pragma unroll
    for (int t = 0; t < TPC; t++) acc[t] = make_float4(0.f, 0.f, 0.f, 0.f);

    int i = 0;
    for (; i + 2 <= cnt; i += 2) {
        const int slot0 = s_list[i];
        const int slot1 = s_list[i + 1];
        // two independent row loads in flight together (MLP=2)
        const float4 r0 =
            reinterpret_cast<const float4*>(g_wout_t + (size_t)s_key[slot0] * DOUT)[tid];
        const float4 r1 =
            reinterpret_cast<const float4*>(g_wout_t + (size_t)s_key[slot1] * DOUT)[tid];
#pragma unroll
        for (int t = 0; t < TPC; t++) {
            const float g0 = s_gl[slot0][t];
            acc[t].x += g0 * r0.x;
            acc[t].y += g0 * r0.y;
            acc[t].z += g0 * r0.z;
            acc[t].w += g0 * r0.w;
        }
#pragma unroll
        for (int t = 0; t < TPC; t++) {
            const float g1 = s_gl[slot1][t];
            acc[t].x += g1 * r1.x;
            acc[t].y += g1 * r1.y;
            acc[t].z += g1 * r1.z;
            acc[t].w += g1 * r1.w;
        }
    }
    if (i < cnt) {                         // tail (odd cnt)
        const int slot0 = s_list[i];
        const float4 r0 =
            reinterpret_cast<const float4*>(g_wout_t + (size_t)s_key[slot0] * DOUT)[tid];
#pragma unroll
        for (int t = 0; t < TPC; t++) {
            const float g0 = s_gl[slot0][t];
            acc[t].x += g0 * r0.x;
            acc[t].y += g0 * r0.y;
            acc[t].z += g0 * r0.z;
            acc[t].w += g0 * r0.w;
        }
    }

#pragma unroll
    for (int t = 0; t < TPC; t++)
        reinterpret_cast<float4*>(out + (size_t)s_tok[t] * DOUT)[tid] = acc[t];
}

// ---------------------------------------------------------------------------
extern "C" void kernel_launch(void* const* d_in, const int* in_sizes, int n_in,
                              void* d_out, int out_size) {
    const float* x     = (const float*)d_in[0];
    const float* w_in  = (const float*)d_in[1];
    const float* w_out = (const float*)d_in[2];
    float* out = (float*)d_out;

    fused_traverse_kernel<<<2 * NTOK, 128>>>(x, w_in, w_out);  // even=traverse, odd=transpose
    scan_scatter_kernel<<<1, 1024>>>();
    accum_kernel<<<NTOK / TPC, 512>>>(out);
}